// round 7
// baseline (speedup 1.0000x reference)
#include <cuda_runtime.h>
#include <math_constants.h>

// ---------------------------------------------------------------------------
// AffineChamferLoss: exact NN via anisotropic 32^3 CSR grid.
// Phase 1: home cell + pruned 26-neighbor box, conditional pruned ring-2,
//          exact slab proofs; unproven -> defer with seed.
// Phase 2: warp-per-query ring continuation (r=3..8, per-ring proof),
//          warp-exhaustive fallback. All bounds exact (boundary cells
//          open-ended outward for clamped outliers).
// ---------------------------------------------------------------------------

#define NMAX   16384
#define G      32
#define CELLS  (G * G * G)     // 32768
#define INFF   3.0e38f
#define RMAX2  8               // phase-2 ring cap before exhaustive fallback

__device__ float4   g_xbuf[NMAX];         // transformed moving pts (set 1)
__device__ float4   g_ybuf[NMAX];         // fixed pts              (set 0)
__device__ int      g_cellid[2][NMAX];
__device__ unsigned g_cnt[2][CELLS];
__device__ int      g_start[2][CELLS + 16];
__device__ unsigned g_cur[2][CELLS];
__device__ float4   g_sort[2][NMAX];
__device__ float    g_mpart[2][128][6];
__device__ int      g_defer[2][NMAX];
__device__ unsigned g_dbest[2][NMAX];
__device__ int      g_dcount[2];

struct GridI {
    float mnx, mny, mnz;
    float hx, hy, hz;
    float ivx, ivy, ivz;
};
__device__ GridI g_grid[2];

// ---- order-preserving float<->uint ----------------------------------------
__device__ __forceinline__ unsigned f2ord(float f) {
    unsigned u = __float_as_uint(f);
    return (u & 0x80000000u) ? ~u : (u | 0x80000000u);
}
__device__ __forceinline__ float ord2f(unsigned u) {
    return (u & 0x80000000u) ? __uint_as_float(u & 0x7fffffffu)
                             : __uint_as_float(~u);
}

// per-axis distance from q to cell i (boundary cells open-ended outward)
__device__ __forceinline__ float axdist(float q, float mn, float h, int i) {
    float lo = fmaf((float)i, h, mn);
    float dl = (i > 0)     ? (lo - q)       : -INFF;
    float dr = (i < G - 1) ? (q - (lo + h)) : -INFF;
    return fmaxf(0.0f, fmaxf(dl, dr));
}

// exact min-distance to all cells OUTSIDE the scanned clipped box of radius R
__device__ __forceinline__ float slab_bound(float fr, float h, int c, int R) {
    float b = INFF;
    if (c - R >= 1)     b = fminf(b, h * (fr + (float)R));
    if (c + R <= G - 2) b = fminf(b, h * ((float)(R + 1) - fr));
    return b;
}

__device__ __forceinline__ void scan_range(const float4* __restrict__ tb,
                                           int s0, int e0, float4 q,
                                           float& best) {
    for (int p = s0; p < e0; ++p) {
        float4 t = tb[p];
        float ax = t.x - q.x, ay = t.y - q.y, az = t.z - q.z;
        float d2 = fmaf(ax, ax, fmaf(ay, ay, az * az));
        best = fminf(best, d2);
    }
}

// ---------------------------------------------------------------------------
// K1: transform + moment partials + zero counts/out/dcount
__global__ void prep_kernel(const float* __restrict__ fx,
                            const float* __restrict__ mv,
                            const float* __restrict__ mat,
                            const float* __restrict__ tr,
                            int nf, int nm, float* out, int nblocks) {
    __shared__ float sm[12];
    int t = threadIdx.x;
    if (t < 12) sm[t] = 0.0f;
    __syncthreads();

    int i = blockIdx.x * 256 + t;

    float mx0 = 0.f, mx1 = 0.f, mx2 = 0.f, mq0 = 0.f, mq1 = 0.f, mq2 = 0.f;
    if (i < nm) {
        float p0 = mv[3*i+0], p1 = mv[3*i+1], p2 = mv[3*i+2];
        float x0 = fmaf(p2, mat[6], fmaf(p1, mat[3], fmaf(p0, mat[0], tr[0])));
        float x1 = fmaf(p2, mat[7], fmaf(p1, mat[4], fmaf(p0, mat[1], tr[1])));
        float x2 = fmaf(p2, mat[8], fmaf(p1, mat[5], fmaf(p0, mat[2], tr[2])));
        g_xbuf[i] = make_float4(x0, x1, x2, 0.0f);
        mx0 = x0; mx1 = x1; mx2 = x2;
        mq0 = x0 * x0; mq1 = x1 * x1; mq2 = x2 * x2;
    }
    float fy0 = 0.f, fy1 = 0.f, fy2 = 0.f, fq0 = 0.f, fq1 = 0.f, fq2 = 0.f;
    if (i < nf) {
        float y0 = fx[3*i+0], y1 = fx[3*i+1], y2 = fx[3*i+2];
        g_ybuf[i] = make_float4(y0, y1, y2, 0.0f);
        fy0 = y0; fy1 = y1; fy2 = y2;
        fq0 = y0 * y0; fq1 = y1 * y1; fq2 = y2 * y2;
    }

    float vals[12] = {fy0, fy1, fy2, fq0, fq1, fq2, mx0, mx1, mx2, mq0, mq1, mq2};
#pragma unroll
    for (int a = 0; a < 12; a++) {
        float v = vals[a];
#pragma unroll
        for (int o = 16; o; o >>= 1) v += __shfl_down_sync(0xffffffffu, v, o);
        if ((t & 31) == 0) atomicAdd(&sm[a], v);
    }
    __syncthreads();
    if (t < 12) g_mpart[t / 6][blockIdx.x][t % 6] = sm[t];

    unsigned* cn = &g_cnt[0][0];
    int tid = blockIdx.x * 256 + t;
    int stride = nblocks * 256;
    for (int k = tid; k < 2 * CELLS; k += stride) cn[k] = 0u;
    if (tid == 0) { out[0] = 0.0f; g_dcount[0] = 0; g_dcount[1] = 0; }
}

// K2: reduce moment partials, build per-axis robust grid geometry
__global__ void grid_kernel(int nblocks, int nf, int nm) {
    __shared__ float bb[12];
    int t = threadIdx.x;
    int slot = t >> 5, lane = t & 31;
    if (slot < 12) {
        int s = slot / 6, k = slot % 6;
        float v = 0.0f;
        for (int j = lane; j < nblocks; j += 32) v += g_mpart[s][j][k];
#pragma unroll
        for (int o = 16; o; o >>= 1) v += __shfl_down_sync(0xffffffffu, v, o);
        if (lane == 0) bb[slot] = v;
    }
    __syncthreads();
    if (t < 2) {
        int s = t;
        float n = (float)(s ? nm : nf);
        float inv = 1.0f / n;
        float mean[3], sig[3];
#pragma unroll
        for (int a = 0; a < 3; a++) {
            mean[a] = bb[s*6+a] * inv;
            float var = bb[s*6+3+a] * inv - mean[a] * mean[a];
            sig[a] = sqrtf(fmaxf(var, 1e-8f));
        }
        GridI gi;
        gi.mnx = mean[0] - 3.0f * sig[0];
        gi.mny = mean[1] - 3.0f * sig[1];
        gi.mnz = mean[2] - 3.0f * sig[2];
        gi.hx = 6.0f * sig[0] / (float)G;
        gi.hy = 6.0f * sig[1] / (float)G;
        gi.hz = 6.0f * sig[2] / (float)G;
        gi.ivx = 1.0f / gi.hx; gi.ivy = 1.0f / gi.hy; gi.ivz = 1.0f / gi.hz;
        g_grid[s] = gi;
    }
}

// K3: cell ids + counts
__global__ void count_kernel(int nf, int nm) {
    int i = blockIdx.x * blockDim.x + threadIdx.x;
    GridI a = g_grid[0], b = g_grid[1];
    if (i < nf) {
        float4 p = g_ybuf[i];
        int ix = min(G - 1, max(0, (int)floorf((p.x - a.mnx) * a.ivx)));
        int iy = min(G - 1, max(0, (int)floorf((p.y - a.mny) * a.ivy)));
        int iz = min(G - 1, max(0, (int)floorf((p.z - a.mnz) * a.ivz)));
        int c = (ix << 10) | (iy << 5) | iz;
        g_cellid[0][i] = c;
        atomicAdd(&g_cnt[0][c], 1u);
    }
    if (i < nm) {
        float4 p = g_xbuf[i];
        int ix = min(G - 1, max(0, (int)floorf((p.x - b.mnx) * b.ivx)));
        int iy = min(G - 1, max(0, (int)floorf((p.y - b.mny) * b.ivy)));
        int iz = min(G - 1, max(0, (int)floorf((p.z - b.mnz) * b.ivz)));
        int c = (ix << 10) | (iy << 5) | iz;
        g_cellid[1][i] = c;
        atomicAdd(&g_cnt[1][c], 1u);
    }
}

// K4: full scan of one set per block (1024 threads x 32 cells each)
__global__ void __launch_bounds__(1024)
scan_kernel() {
    __shared__ unsigned wsm[32];
    int s = blockIdx.x;
    int t = threadIdx.x;
    int lane = t & 31, wp = t >> 5;

    unsigned cnts[32];
    const uint4* c4 = reinterpret_cast<const uint4*>(&g_cnt[s][0]);
#pragma unroll
    for (int j = 0; j < 8; j++) {
        uint4 v = c4[t * 8 + j];
        cnts[j*4+0] = v.x; cnts[j*4+1] = v.y; cnts[j*4+2] = v.z; cnts[j*4+3] = v.w;
    }
    unsigned tot = 0;
#pragma unroll
    for (int j = 0; j < 32; j++) tot += cnts[j];

    unsigned inc = tot;
#pragma unroll
    for (int o = 1; o < 32; o <<= 1) {
        unsigned n = __shfl_up_sync(0xffffffffu, inc, o);
        if (lane >= o) inc += n;
    }
    if (lane == 31) wsm[wp] = inc;
    __syncthreads();
    if (wp == 0) {
        unsigned w = wsm[lane];
#pragma unroll
        for (int o = 1; o < 32; o <<= 1) {
            unsigned n = __shfl_up_sync(0xffffffffu, w, o);
            if (lane >= o) w += n;
        }
        wsm[lane] = w;
    }
    __syncthreads();
    unsigned run = (wp ? wsm[wp - 1] : 0u) + inc - tot;

    int starts[32];
#pragma unroll
    for (int j = 0; j < 32; j++) { starts[j] = (int)run; run += cnts[j]; }

    int4* st4 = reinterpret_cast<int4*>(&g_start[s][0]);
    int4* cu4 = reinterpret_cast<int4*>(&g_cur[s][0]);
#pragma unroll
    for (int j = 0; j < 8; j++) {
        int4 v = make_int4(starts[j*4+0], starts[j*4+1], starts[j*4+2], starts[j*4+3]);
        st4[t * 8 + j] = v;
        cu4[t * 8 + j] = v;
    }
    if (t == 1023) g_start[s][CELLS] = (int)run;
}

// K5: scatter into CSR order
__global__ void scatter_kernel(int nf, int nm) {
    int i = blockIdx.x * blockDim.x + threadIdx.x;
    if (i < nf) {
        int c = g_cellid[0][i];
        unsigned p = atomicAdd(&g_cur[0][c], 1u);
        g_sort[0][p] = g_ybuf[i];
    }
    if (i < nm) {
        int c = g_cellid[1][i];
        unsigned p = atomicAdd(&g_cur[1][c], 1u);
        g_sort[1][p] = g_xbuf[i];
    }
}

// K6: phase-1 exact NN (home + pruned 26 neighbors + pruned ring 2)
__global__ void __launch_bounds__(256)
query_kernel(float* out, int nm, int nf) {
    const int dir = blockIdx.y;                 // 0: mov->fixed, 1: fixed->mov
    const int nq = dir ? nf : nm;
    const float4* __restrict__ qb = dir ? g_ybuf : g_xbuf;
    const float4* __restrict__ tb = g_sort[dir];
    const int*    __restrict__ cs = &g_start[dir][0];
    GridI gi = g_grid[dir];

    int qi = blockIdx.x * 256 + threadIdx.x;
    float acc = 0.0f;
    if (qi < nq) {
        float4 q = qb[qi];
        float rx = (q.x - gi.mnx) * gi.ivx;
        float ry = (q.y - gi.mny) * gi.ivy;
        float rz = (q.z - gi.mnz) * gi.ivz;
        int cx = min(G - 1, max(0, (int)floorf(rx)));
        int cy = min(G - 1, max(0, (int)floorf(ry)));
        int cz = min(G - 1, max(0, (int)floorf(rz)));
        float fxr = rx - (float)cx;
        float fyr = ry - (float)cy;
        float fzr = rz - (float)cz;

        int home = (cx << 10) | (cy << 5) | cz;
        float best = INFF;
        scan_range(tb, cs[home], cs[home + 1], q, best);

        // per-axis squared distances for offsets -1, 0, +1 (INF if off-grid)
        float dxs[3], dys[3], dzs[3];
#pragma unroll
        for (int k = 0; k < 3; k++) {
            int ix = cx + k - 1;
            float d = axdist(q.x, gi.mnx, gi.hx, ix);
            dxs[k] = ((unsigned)ix < G) ? d * d : INFF;
            int iy = cy + k - 1;
            d = axdist(q.y, gi.mny, gi.hy, iy);
            dys[k] = ((unsigned)iy < G) ? d * d : INFF;
            int iz = cz + k - 1;
            d = axdist(q.z, gi.mnz, gi.hz, iz);
            dzs[k] = ((unsigned)iz < G) ? d * d : INFF;
        }

        // 26 neighbors with exact 3D box-bound pruning
#pragma unroll
        for (int a = 0; a < 3; a++) {
#pragma unroll
            for (int b = 0; b < 3; b++) {
                float dab = dxs[a] + dys[b];
#pragma unroll
                for (int c = 0; c < 3; c++) {
                    if (a == 1 && b == 1 && c == 1) continue;
                    float bnd = dab + dzs[c];
                    if (bnd < best) {
                        int cell = ((cx + a - 1) << 10) | ((cy + b - 1) << 5)
                                 | (cz + c - 1);
                        scan_range(tb, cs[cell], cs[cell + 1], q, best);
                    }
                }
            }
        }

        float b1 = fminf(fminf(slab_bound(fxr, gi.hx, cx, 1),
                               slab_bound(fyr, gi.hy, cy, 1)),
                         slab_bound(fzr, gi.hz, cz, 1));
        bool done = (b1 * b1 >= best);

        if (!done) {
            // ring-2 shell, clipped, per-cell pruned
            int x2lo = max(cx - 2, 0), x2hi = min(cx + 2, G - 1);
            int y2lo = max(cy - 2, 0), y2hi = min(cy + 2, G - 1);
            for (int ix = x2lo; ix <= x2hi; ++ix) {
                int adx = abs(ix - cx);
                float ddx = axdist(q.x, gi.mnx, gi.hx, ix);
                float dx2 = ddx * ddx;
                if (dx2 >= best) continue;
                for (int iy = y2lo; iy <= y2hi; ++iy) {
                    int ad = max(adx, abs(iy - cy));
                    float ddy = axdist(q.y, gi.mny, gi.hy, iy);
                    float dxy2 = fmaf(ddy, ddy, dx2);
                    if (dxy2 >= best) continue;
                    int base = (ix << 10) | (iy << 5);
                    int zlo, zhi;
                    if (ad == 2) { zlo = max(cz - 2, 0); zhi = min(cz + 2, G - 1); }
                    else         { zlo = cz - 2;         zhi = cz + 2; }
                    for (int iz = zlo; iz <= zhi; ++iz) {
                        if (ad != 2 && iz != cz - 2 && iz != cz + 2) continue;
                        if ((unsigned)iz >= G) continue;
                        float ddz = axdist(q.z, gi.mnz, gi.hz, iz);
                        if (fmaf(ddz, ddz, dxy2) < best)
                            scan_range(tb, cs[base | iz], cs[(base | iz) + 1], q, best);
                    }
                }
            }
            float b2 = fminf(fminf(slab_bound(fxr, gi.hx, cx, 2),
                                   slab_bound(fyr, gi.hy, cy, 2)),
                             slab_bound(fzr, gi.hz, cz, 2));
            done = (b2 * b2 >= best);
        }

        if (done) {
            acc = best / (float)nq;
        } else {
            int slot = atomicAdd(&g_dcount[dir], 1);
            g_defer[dir][slot] = qi;
            g_dbest[dir][slot] = f2ord(best);
        }
    }

#pragma unroll
    for (int o = 16; o; o >>= 1) acc += __shfl_down_sync(0xffffffffu, acc, o);
    __shared__ float ws[8];
    int lane = threadIdx.x & 31, warp = threadIdx.x >> 5;
    if (lane == 0) ws[warp] = acc;
    __syncthreads();
    if (warp == 0) {
        acc = (lane < 8) ? ws[lane] : 0.0f;
#pragma unroll
        for (int o = 4; o; o >>= 1) acc += __shfl_down_sync(0xffffffffu, acc, o);
        if (lane == 0) atomicAdd(out, acc);
    }
}

// K7: warp-per-deferred-query ring continuation + exhaustive fallback
__global__ void __launch_bounds__(256)
ring_kernel(int nm, int nf) {
    int gw = (blockIdx.x * 256 + threadIdx.x) >> 5;
    int lane = threadIdx.x & 31;
    int nwarps = (gridDim.x * 256) >> 5;

    int cnt0 = min(g_dcount[0], NMAX);
    int cnt1 = min(g_dcount[1], NMAX);
    int total = cnt0 + cnt1;

    for (int it = gw; it < total; it += nwarps) {
        int dir = (it < cnt0) ? 1 : 0;          // note: remap below
        int slot;
        if (it < cnt0) { dir = 0; slot = it; }
        else           { dir = 1; slot = it - cnt0; }
        int qi = g_defer[dir][slot];
        const float4* __restrict__ qb = dir ? g_ybuf : g_xbuf;
        const float4* __restrict__ tb = g_sort[dir];
        const int*    __restrict__ cs = &g_start[dir][0];
        GridI gi = g_grid[dir];
        int nt = dir ? nm : nf;

        float4 q = qb[qi];
        float best = ord2f(g_dbest[dir][slot]);

        float rx = (q.x - gi.mnx) * gi.ivx;
        float ry = (q.y - gi.mny) * gi.ivy;
        float rz = (q.z - gi.mnz) * gi.ivz;
        int cx = min(G - 1, max(0, (int)floorf(rx)));
        int cy = min(G - 1, max(0, (int)floorf(ry)));
        int cz = min(G - 1, max(0, (int)floorf(rz)));
        float fxr = rx - (float)cx;
        float fyr = ry - (float)cy;
        float fzr = rz - (float)cz;
        int rmx = max(max(max(cx, G - 1 - cx), max(cy, G - 1 - cy)),
                      max(cz, G - 1 - cz));

        bool proven = false;
        for (int r = 3; r <= RMAX2; ++r) {
            float bp = fminf(fminf(slab_bound(fxr, gi.hx, cx, r - 1),
                                   slab_bound(fyr, gi.hy, cy, r - 1)),
                             slab_bound(fzr, gi.hz, cz, r - 1));
            if (bp * bp >= best) { proven = true; break; }
            if (r > rmx) { proven = true; break; }

            int side = 2 * r + 1;
            int nc = side * side * side;
            float lbest = best;
            for (int k = lane; k < nc; k += 32) {
                int a = k / (side * side);
                int rem = k - a * side * side;
                int b = rem / side;
                int c = rem - b * side;
                a -= r; b -= r; c -= r;
                if (max(max(abs(a), abs(b)), abs(c)) != r) continue;
                int ix = cx + a, iy = cy + b, iz = cz + c;
                if ((unsigned)ix >= G || (unsigned)iy >= G || (unsigned)iz >= G)
                    continue;
                float ddx = axdist(q.x, gi.mnx, gi.hx, ix);
                float ddy = axdist(q.y, gi.mny, gi.hy, iy);
                float ddz = axdist(q.z, gi.mnz, gi.hz, iz);
                float bnd = fmaf(ddx, ddx, fmaf(ddy, ddy, ddz * ddz));
                if (bnd >= lbest) continue;
                int cell = (ix << 10) | (iy << 5) | iz;
                scan_range(tb, cs[cell], cs[cell + 1], q, lbest);
            }
#pragma unroll
            for (int o = 16; o; o >>= 1)
                lbest = fminf(lbest, __shfl_xor_sync(0xffffffffu, lbest, o));
            best = lbest;
        }

        if (!proven) {
            // exhaustive fallback (exact regardless of seed)
            float lbest = best;
            for (int p = lane; p < nt; p += 32) {
                float4 t = tb[p];
                float ax = t.x - q.x, ay = t.y - q.y, az = t.z - q.z;
                float d2 = fmaf(ax, ax, fmaf(ay, ay, az * az));
                lbest = fminf(lbest, d2);
            }
#pragma unroll
            for (int o = 16; o; o >>= 1)
                lbest = fminf(lbest, __shfl_xor_sync(0xffffffffu, lbest, o));
            best = lbest;
        }

        if (lane == 0) g_dbest[dir][slot] = f2ord(best);
    }
}

// K8: sum deferred query means
__global__ void __launch_bounds__(256)
fin_kernel(float* out, int nm, int nf) {
    int cnt0 = min(g_dcount[0], NMAX);
    int cnt1 = min(g_dcount[1], NMAX);
    int total = cnt0 + cnt1;
    float acc = 0.0f;
    for (int i = blockIdx.x * 256 + threadIdx.x; i < total;
         i += gridDim.x * 256) {
        int dir = (i < cnt0) ? 0 : 1;
        int slot = (dir == 0) ? i : (i - cnt0);
        float nq = dir ? (float)nf : (float)nm;
        acc += ord2f(g_dbest[dir][slot]) / nq;
    }
#pragma unroll
    for (int o = 16; o; o >>= 1) acc += __shfl_down_sync(0xffffffffu, acc, o);
    __shared__ float ws[8];
    int lane = threadIdx.x & 31, warp = threadIdx.x >> 5;
    if (lane == 0) ws[warp] = acc;
    __syncthreads();
    if (warp == 0) {
        acc = (lane < 8) ? ws[lane] : 0.0f;
#pragma unroll
        for (int o = 4; o; o >>= 1) acc += __shfl_down_sync(0xffffffffu, acc, o);
        if (lane == 0) atomicAdd(out, acc);
    }
}

// ---------------------------------------------------------------------------
extern "C" void kernel_launch(void* const* d_in, const int* in_sizes, int n_in,
                              void* d_out, int out_size) {
    const float* fx  = (const float*)d_in[0];
    const float* mv  = (const float*)d_in[1];
    const float* mat = (const float*)d_in[2];
    const float* tr  = (const float*)d_in[3];
    float* out = (float*)d_out;

    int nf = in_sizes[0] / 3;
    int nm = in_sizes[1] / 3;
    int nmax = nf > nm ? nf : nm;
    int pblk = (nmax + 255) / 256;
    if (pblk > 128) pblk = 128;

    prep_kernel<<<pblk, 256>>>(fx, mv, mat, tr, nf, nm, out, pblk);
    grid_kernel<<<1, 384>>>(pblk, nf, nm);
    count_kernel<<<pblk, 256>>>(nf, nm);
    scan_kernel<<<2, 1024>>>();
    scatter_kernel<<<pblk, 256>>>(nf, nm);
    query_kernel<<<dim3((nmax + 255) / 256, 2), 256>>>(out, nm, nf);
    ring_kernel<<<148, 256>>>(nm, nf);
    fin_kernel<<<16, 256>>>(out, nm, nf);
}

// round 8
// speedup vs baseline: 7.9561x; 7.9561x over previous
#include <cuda_runtime.h>
#include <math_constants.h>

// ---------------------------------------------------------------------------
// AffineChamferLoss: exact NN via anisotropic 32^3 CSR grid.
// Phase 1 (per-thread, sorted queries): home cell + box-bound-pruned 26
//   neighbors + pruned ring-2, exact slab proofs; unproven -> defer w/ seed.
// Phase 2 (warp per deferred query): sample upper bound, then sweep all
//   (ix,iy) z-columns with exact dxy^2 pruning; each surviving column's
//   admissible z-range is one contiguous CSR range. Exact; boundary cells
//   open-ended outward (clamped outliers).
// ---------------------------------------------------------------------------

#define NMAX   16384
#define G      32
#define CELLS  (G * G * G)     // 32768
#define SEGC   4096            // cells per scan segment
#define INFF   3.0e38f

__device__ float4   g_xbuf[NMAX];         // transformed moving pts (set 1)
__device__ float4   g_ybuf[NMAX];         // fixed pts              (set 0)
__device__ int      g_cellid[2][NMAX];
__device__ unsigned g_cnt[2][CELLS];
__device__ int      g_start[2][CELLS + 16];
__device__ unsigned g_cur[2][CELLS];
__device__ float4   g_sort[2][NMAX];
__device__ float    g_mpart[2][128][6];
__device__ unsigned g_segsum[2][8];
__device__ unsigned g_segoff[2][8];
__device__ int      g_defer[2][NMAX];
__device__ unsigned g_dbest[2][NMAX];
__device__ int      g_dcount[2];

struct GridI {
    float mnx, mny, mnz;
    float hx, hy, hz;
    float ivx, ivy, ivz;
};
__device__ GridI g_grid[2];

// ---- order-preserving float<->uint ----------------------------------------
__device__ __forceinline__ unsigned f2ord(float f) {
    unsigned u = __float_as_uint(f);
    return (u & 0x80000000u) ? ~u : (u | 0x80000000u);
}
__device__ __forceinline__ float ord2f(unsigned u) {
    return (u & 0x80000000u) ? __uint_as_float(u & 0x7fffffffu)
                             : __uint_as_float(~u);
}

// per-axis distance lower bound from q to cell i (boundary cells open outward)
__device__ __forceinline__ float axdist(float q, float mn, float h, int i) {
    float lo = fmaf((float)i, h, mn);
    float dl = (i > 0)     ? (lo - q)       : -INFF;
    float dr = (i < G - 1) ? (q - (lo + h)) : -INFF;
    return fmaxf(0.0f, fmaxf(dl, dr));
}

// exact min-distance to all cells OUTSIDE the scanned clipped box of radius R
__device__ __forceinline__ float slab_bound(float fr, float h, int c, int R) {
    float b = INFF;
    if (c - R >= 1)     b = fminf(b, h * (fr + (float)R));
    if (c + R <= G - 2) b = fminf(b, h * ((float)(R + 1) - fr));
    return b;
}

__device__ __forceinline__ void scan_range(const float4* __restrict__ tb,
                                           int s0, int e0, float4 q,
                                           float& best) {
    for (int p = s0; p < e0; ++p) {
        float4 t = tb[p];
        float ax = t.x - q.x, ay = t.y - q.y, az = t.z - q.z;
        float d2 = fmaf(ax, ax, fmaf(ay, ay, az * az));
        best = fminf(best, d2);
    }
}

// ---- 256-thread block exclusive scan ---------------------------------------
__device__ __forceinline__ unsigned excl_scan_256(unsigned v, unsigned* wsm) {
    int lane = threadIdx.x & 31, wp = threadIdx.x >> 5;
    unsigned inc = v;
#pragma unroll
    for (int o = 1; o < 32; o <<= 1) {
        unsigned n = __shfl_up_sync(0xffffffffu, inc, o);
        if (lane >= o) inc += n;
    }
    if (lane == 31) wsm[wp] = inc;
    __syncthreads();
    if (wp == 0) {
        unsigned ws = (lane < 8) ? wsm[lane] : 0u;
#pragma unroll
        for (int o = 1; o < 8; o <<= 1) {
            unsigned n = __shfl_up_sync(0xffffffffu, ws, o);
            if (lane >= o) ws += n;
        }
        if (lane < 8) wsm[lane] = ws;
    }
    __syncthreads();
    unsigned off = wp ? wsm[wp - 1] : 0u;
    return off + inc - v;
}

// ---------------------------------------------------------------------------
// K1: transform + moment partials + zero counts/out/dcount
__global__ void prep_kernel(const float* __restrict__ fx,
                            const float* __restrict__ mv,
                            const float* __restrict__ mat,
                            const float* __restrict__ tr,
                            int nf, int nm, float* out, int nblocks) {
    __shared__ float sm[12];
    int t = threadIdx.x;
    if (t < 12) sm[t] = 0.0f;
    __syncthreads();

    int i = blockIdx.x * 256 + t;

    float mx0 = 0.f, mx1 = 0.f, mx2 = 0.f, mq0 = 0.f, mq1 = 0.f, mq2 = 0.f;
    if (i < nm) {
        float p0 = mv[3*i+0], p1 = mv[3*i+1], p2 = mv[3*i+2];
        float x0 = fmaf(p2, mat[6], fmaf(p1, mat[3], fmaf(p0, mat[0], tr[0])));
        float x1 = fmaf(p2, mat[7], fmaf(p1, mat[4], fmaf(p0, mat[1], tr[1])));
        float x2 = fmaf(p2, mat[8], fmaf(p1, mat[5], fmaf(p0, mat[2], tr[2])));
        g_xbuf[i] = make_float4(x0, x1, x2, 0.0f);
        mx0 = x0; mx1 = x1; mx2 = x2;
        mq0 = x0 * x0; mq1 = x1 * x1; mq2 = x2 * x2;
    }
    float fy0 = 0.f, fy1 = 0.f, fy2 = 0.f, fq0 = 0.f, fq1 = 0.f, fq2 = 0.f;
    if (i < nf) {
        float y0 = fx[3*i+0], y1 = fx[3*i+1], y2 = fx[3*i+2];
        g_ybuf[i] = make_float4(y0, y1, y2, 0.0f);
        fy0 = y0; fy1 = y1; fy2 = y2;
        fq0 = y0 * y0; fq1 = y1 * y1; fq2 = y2 * y2;
    }

    float vals[12] = {fy0, fy1, fy2, fq0, fq1, fq2, mx0, mx1, mx2, mq0, mq1, mq2};
#pragma unroll
    for (int a = 0; a < 12; a++) {
        float v = vals[a];
#pragma unroll
        for (int o = 16; o; o >>= 1) v += __shfl_down_sync(0xffffffffu, v, o);
        if ((t & 31) == 0) atomicAdd(&sm[a], v);
    }
    __syncthreads();
    if (t < 12) g_mpart[t / 6][blockIdx.x][t % 6] = sm[t];

    unsigned* cn = &g_cnt[0][0];
    int tid = blockIdx.x * 256 + t;
    int stride = nblocks * 256;
    for (int k = tid; k < 2 * CELLS; k += stride) cn[k] = 0u;
    if (tid == 0) { out[0] = 0.0f; g_dcount[0] = 0; g_dcount[1] = 0; }
}

// K2: reduce moment partials, build per-axis robust grid geometry
__global__ void grid_kernel(int nblocks, int nf, int nm) {
    __shared__ float bb[12];
    int t = threadIdx.x;
    int slot = t >> 5, lane = t & 31;
    if (slot < 12) {
        int s = slot / 6, k = slot % 6;
        float v = 0.0f;
        for (int j = lane; j < nblocks; j += 32) v += g_mpart[s][j][k];
#pragma unroll
        for (int o = 16; o; o >>= 1) v += __shfl_down_sync(0xffffffffu, v, o);
        if (lane == 0) bb[slot] = v;
    }
    __syncthreads();
    if (t < 2) {
        int s = t;
        float n = (float)(s ? nm : nf);
        float inv = 1.0f / n;
        float mean[3], sig[3];
#pragma unroll
        for (int a = 0; a < 3; a++) {
            mean[a] = bb[s*6+a] * inv;
            float var = bb[s*6+3+a] * inv - mean[a] * mean[a];
            sig[a] = sqrtf(fmaxf(var, 1e-8f));
        }
        GridI gi;
        gi.mnx = mean[0] - 3.0f * sig[0];
        gi.mny = mean[1] - 3.0f * sig[1];
        gi.mnz = mean[2] - 3.0f * sig[2];
        gi.hx = 6.0f * sig[0] / (float)G;
        gi.hy = 6.0f * sig[1] / (float)G;
        gi.hz = 6.0f * sig[2] / (float)G;
        gi.ivx = 1.0f / gi.hx; gi.ivy = 1.0f / gi.hy; gi.ivz = 1.0f / gi.hz;
        g_grid[s] = gi;
    }
}

// K3: cell ids + counts
__global__ void count_kernel(int nf, int nm) {
    int i = blockIdx.x * blockDim.x + threadIdx.x;
    GridI a = g_grid[0], b = g_grid[1];
    if (i < nf) {
        float4 p = g_ybuf[i];
        int ix = min(G - 1, max(0, (int)floorf((p.x - a.mnx) * a.ivx)));
        int iy = min(G - 1, max(0, (int)floorf((p.y - a.mny) * a.ivy)));
        int iz = min(G - 1, max(0, (int)floorf((p.z - a.mnz) * a.ivz)));
        int c = (ix << 10) | (iy << 5) | iz;
        g_cellid[0][i] = c;
        atomicAdd(&g_cnt[0][c], 1u);
    }
    if (i < nm) {
        float4 p = g_xbuf[i];
        int ix = min(G - 1, max(0, (int)floorf((p.x - b.mnx) * b.ivx)));
        int iy = min(G - 1, max(0, (int)floorf((p.y - b.mny) * b.ivy)));
        int iz = min(G - 1, max(0, (int)floorf((p.z - b.mnz) * b.ivz)));
        int c = (ix << 10) | (iy << 5) | iz;
        g_cellid[1][i] = c;
        atomicAdd(&g_cnt[1][c], 1u);
    }
}

// K4: local scan of 4096-cell segments (16 blocks: set = b>>3, seg = b&7)
__global__ void __launch_bounds__(256)
scanA_kernel() {
    __shared__ unsigned wsm[8];
    int s = blockIdx.x >> 3, seg = blockIdx.x & 7;
    int t = threadIdx.x;
    const uint4* c4 = reinterpret_cast<const uint4*>(&g_cnt[s][seg * SEGC]);
    unsigned cnts[16];
#pragma unroll
    for (int j = 0; j < 4; j++) {
        uint4 v = c4[t * 4 + j];
        cnts[j*4+0] = v.x; cnts[j*4+1] = v.y; cnts[j*4+2] = v.z; cnts[j*4+3] = v.w;
    }
    unsigned tot = 0;
#pragma unroll
    for (int j = 0; j < 16; j++) tot += cnts[j];

    unsigned e = excl_scan_256(tot, wsm);

    unsigned run = e;
    int st[16];
#pragma unroll
    for (int j = 0; j < 16; j++) { st[j] = (int)run; run += cnts[j]; }

    int4* st4 = reinterpret_cast<int4*>(&g_start[s][seg * SEGC]);
#pragma unroll
    for (int j = 0; j < 4; j++)
        st4[t * 4 + j] = make_int4(st[j*4+0], st[j*4+1], st[j*4+2], st[j*4+3]);
    if (t == 255) g_segsum[s][seg] = run;
}

// K5: 1-warp scan of segment sums for both sets
__global__ void scanB_kernel() {
    int lane = threadIdx.x;
    for (int s = 0; s < 2; ++s) {
        unsigned v = (lane < 8) ? g_segsum[s][lane] : 0u;
        unsigned inc = v;
#pragma unroll
        for (int o = 1; o < 8; o <<= 1) {
            unsigned n = __shfl_up_sync(0xffffffffu, inc, o);
            if (lane >= o) inc += n;
        }
        if (lane < 8) g_segoff[s][lane] = inc - v;
        if (lane == 7) g_start[s][CELLS] = (int)inc;
    }
}

// K6: apply segment offsets, write cursors
__global__ void __launch_bounds__(256)
scanC_kernel() {
    int s = blockIdx.x >> 3, seg = blockIdx.x & 7;
    int t = threadIdx.x;
    int off = (int)g_segoff[s][seg];
    int4* st4 = reinterpret_cast<int4*>(&g_start[s][seg * SEGC]);
    int4* cu4 = reinterpret_cast<int4*>(&g_cur[s][seg * SEGC]);
#pragma unroll
    for (int j = 0; j < 4; j++) {
        int4 v = st4[t * 4 + j];
        v.x += off; v.y += off; v.z += off; v.w += off;
        st4[t * 4 + j] = v;
        cu4[t * 4 + j] = v;
    }
}

// K7: scatter into CSR order
__global__ void scatter_kernel(int nf, int nm) {
    int i = blockIdx.x * blockDim.x + threadIdx.x;
    if (i < nf) {
        int c = g_cellid[0][i];
        unsigned p = atomicAdd(&g_cur[0][c], 1u);
        g_sort[0][p] = g_ybuf[i];
    }
    if (i < nm) {
        int c = g_cellid[1][i];
        unsigned p = atomicAdd(&g_cur[1][c], 1u);
        g_sort[1][p] = g_xbuf[i];
    }
}

// K8: phase-1 exact NN, SORTED queries; unproven -> defer
__global__ void __launch_bounds__(256)
query_kernel(float* out, int nm, int nf) {
    const int dir = blockIdx.y;                 // 0: mov->fixed, 1: fixed->mov
    const int nq = dir ? nf : nm;
    const float4* __restrict__ qb = g_sort[1 - dir];   // sorted queries
    const float4* __restrict__ tb = g_sort[dir];
    const int*    __restrict__ cs = &g_start[dir][0];
    GridI gi = g_grid[dir];

    int qi = blockIdx.x * 256 + threadIdx.x;
    float acc = 0.0f;
    if (qi < nq) {
        float4 q = qb[qi];
        float rx = (q.x - gi.mnx) * gi.ivx;
        float ry = (q.y - gi.mny) * gi.ivy;
        float rz = (q.z - gi.mnz) * gi.ivz;
        int cx = min(G - 1, max(0, (int)floorf(rx)));
        int cy = min(G - 1, max(0, (int)floorf(ry)));
        int cz = min(G - 1, max(0, (int)floorf(rz)));
        float fxr = rx - (float)cx;
        float fyr = ry - (float)cy;
        float fzr = rz - (float)cz;

        int home = (cx << 10) | (cy << 5) | cz;
        float best = INFF;
        scan_range(tb, cs[home], cs[home + 1], q, best);

        float dxs[3], dys[3], dzs[3];
#pragma unroll
        for (int k = 0; k < 3; k++) {
            int ix = cx + k - 1;
            float d = axdist(q.x, gi.mnx, gi.hx, ix);
            dxs[k] = ((unsigned)ix < G) ? d * d : INFF;
            int iy = cy + k - 1;
            d = axdist(q.y, gi.mny, gi.hy, iy);
            dys[k] = ((unsigned)iy < G) ? d * d : INFF;
            int iz = cz + k - 1;
            d = axdist(q.z, gi.mnz, gi.hz, iz);
            dzs[k] = ((unsigned)iz < G) ? d * d : INFF;
        }

#pragma unroll
        for (int a = 0; a < 3; a++) {
#pragma unroll
            for (int b = 0; b < 3; b++) {
                float dab = dxs[a] + dys[b];
#pragma unroll
                for (int c = 0; c < 3; c++) {
                    if (a == 1 && b == 1 && c == 1) continue;
                    float bnd = dab + dzs[c];
                    if (bnd < best) {
                        int cell = ((cx + a - 1) << 10) | ((cy + b - 1) << 5)
                                 | (cz + c - 1);
                        scan_range(tb, cs[cell], cs[cell + 1], q, best);
                    }
                }
            }
        }

        float b1 = fminf(fminf(slab_bound(fxr, gi.hx, cx, 1),
                               slab_bound(fyr, gi.hy, cy, 1)),
                         slab_bound(fzr, gi.hz, cz, 1));
        bool done = (b1 * b1 >= best);

        if (!done) {
            int x2lo = max(cx - 2, 0), x2hi = min(cx + 2, G - 1);
            int y2lo = max(cy - 2, 0), y2hi = min(cy + 2, G - 1);
            for (int ix = x2lo; ix <= x2hi; ++ix) {
                int adx = abs(ix - cx);
                float ddx = axdist(q.x, gi.mnx, gi.hx, ix);
                float dx2 = ddx * ddx;
                if (dx2 >= best) continue;
                for (int iy = y2lo; iy <= y2hi; ++iy) {
                    int ad = max(adx, abs(iy - cy));
                    float ddy = axdist(q.y, gi.mny, gi.hy, iy);
                    float dxy2 = fmaf(ddy, ddy, dx2);
                    if (dxy2 >= best) continue;
                    int base = (ix << 10) | (iy << 5);
                    int zlo, zhi;
                    if (ad == 2) { zlo = max(cz - 2, 0); zhi = min(cz + 2, G - 1); }
                    else         { zlo = cz - 2;         zhi = cz + 2; }
                    for (int iz = zlo; iz <= zhi; ++iz) {
                        if (ad != 2 && iz != cz - 2 && iz != cz + 2) continue;
                        if ((unsigned)iz >= G) continue;
                        float ddz = axdist(q.z, gi.mnz, gi.hz, iz);
                        if (fmaf(ddz, ddz, dxy2) < best)
                            scan_range(tb, cs[base | iz], cs[(base | iz) + 1],
                                       q, best);
                    }
                }
            }
            float b2 = fminf(fminf(slab_bound(fxr, gi.hx, cx, 2),
                                   slab_bound(fyr, gi.hy, cy, 2)),
                             slab_bound(fzr, gi.hz, cz, 2));
            done = (b2 * b2 >= best);
        }

        if (done) {
            acc = best / (float)nq;
        } else {
            int slot = atomicAdd(&g_dcount[dir], 1);
            g_defer[dir][slot] = qi;                 // sorted index
            g_dbest[dir][slot] = f2ord(best);
        }
    }

#pragma unroll
    for (int o = 16; o; o >>= 1) acc += __shfl_down_sync(0xffffffffu, acc, o);
    __shared__ float ws[8];
    int lane = threadIdx.x & 31, warp = threadIdx.x >> 5;
    if (lane == 0) ws[warp] = acc;
    __syncthreads();
    if (warp == 0) {
        acc = (lane < 8) ? ws[lane] : 0.0f;
#pragma unroll
        for (int o = 4; o; o >>= 1) acc += __shfl_down_sync(0xffffffffu, acc, o);
        if (lane == 0) atomicAdd(out, acc);
    }
}

// K9: warp-per-deferred-query z-column sweep (exact)
__global__ void __launch_bounds__(256)
tail_kernel(int nm, int nf) {
    int gw = (blockIdx.x * 256 + threadIdx.x) >> 5;
    int lane = threadIdx.x & 31;
    int nwarps = (gridDim.x * 256) >> 5;

    int cnt0 = min(g_dcount[0], NMAX);
    int cnt1 = min(g_dcount[1], NMAX);
    int total = cnt0 + cnt1;

    for (int it = gw; it < total; it += nwarps) {
        int dir, slot;
        if (it < cnt0) { dir = 0; slot = it; }
        else           { dir = 1; slot = it - cnt0; }
        int qi = g_defer[dir][slot];
        const float4* __restrict__ qb = g_sort[1 - dir];
        const float4* __restrict__ tb = g_sort[dir];
        const int*    __restrict__ cs = &g_start[dir][0];
        GridI gi = g_grid[dir];
        int nt = dir ? nm : nf;

        float4 q = qb[qi];
        float lbest = ord2f(g_dbest[dir][slot]);

        // strided 32-point sample: finite upper bound
        {
            int p = lane * (nt >> 5);
            if (p < nt) {
                float4 t = tb[p];
                float ax = t.x - q.x, ay = t.y - q.y, az = t.z - q.z;
                lbest = fminf(lbest, fmaf(ax, ax, fmaf(ay, ay, az * az)));
            }
        }
#pragma unroll
        for (int o = 16; o; o >>= 1)
            lbest = fminf(lbest, __shfl_xor_sync(0xffffffffu, lbest, o));

        float uz = (q.z - gi.mnz) * gi.ivz;     // z in cell coords

        // sweep all (ix,iy) columns, lanes strided
        for (int col = lane; col < G * G; col += 32) {
            int ix = col >> 5, iy = col & 31;
            float ddx = axdist(q.x, gi.mnx, gi.hx, ix);
            float ddy = axdist(q.y, gi.mny, gi.hy, iy);
            float dxy2 = fmaf(ddx, ddx, ddy * ddy);
            float rem = lbest - dxy2;
            if (rem <= 0.0f) continue;
            float sv = sqrtf(rem) * gi.ivz;
            int zlo = (int)floorf(uz - sv);
            int zhi = (int)floorf(uz + sv);
            zlo = min(G - 1, max(0, zlo));      // clamps keep open boundary
            zhi = min(G - 1, max(0, zhi));      // cells included when outside
            int base = (ix << 10) | (iy << 5);
            scan_range(tb, cs[base + zlo], cs[base + zhi + 1], q, lbest);
        }

#pragma unroll
        for (int o = 16; o; o >>= 1)
            lbest = fminf(lbest, __shfl_xor_sync(0xffffffffu, lbest, o));
        if (lane == 0) g_dbest[dir][slot] = f2ord(lbest);
    }
}

// K10: sum deferred query means
__global__ void __launch_bounds__(256)
fin_kernel(float* out, int nm, int nf) {
    int cnt0 = min(g_dcount[0], NMAX);
    int cnt1 = min(g_dcount[1], NMAX);
    int total = cnt0 + cnt1;
    float acc = 0.0f;
    for (int i = blockIdx.x * 256 + threadIdx.x; i < total;
         i += gridDim.x * 256) {
        int dir = (i < cnt0) ? 0 : 1;
        int slot = (dir == 0) ? i : (i - cnt0);
        float nq = dir ? (float)nf : (float)nm;
        acc += ord2f(g_dbest[dir][slot]) / nq;
    }
#pragma unroll
    for (int o = 16; o; o >>= 1) acc += __shfl_down_sync(0xffffffffu, acc, o);
    __shared__ float ws[8];
    int lane = threadIdx.x & 31, warp = threadIdx.x >> 5;
    if (lane == 0) ws[warp] = acc;
    __syncthreads();
    if (warp == 0) {
        acc = (lane < 8) ? ws[lane] : 0.0f;
#pragma unroll
        for (int o = 4; o; o >>= 1) acc += __shfl_down_sync(0xffffffffu, acc, o);
        if (lane == 0) atomicAdd(out, acc);
    }
}

// ---------------------------------------------------------------------------
extern "C" void kernel_launch(void* const* d_in, const int* in_sizes, int n_in,
                              void* d_out, int out_size) {
    const float* fx  = (const float*)d_in[0];
    const float* mv  = (const float*)d_in[1];
    const float* mat = (const float*)d_in[2];
    const float* tr  = (const float*)d_in[3];
    float* out = (float*)d_out;

    int nf = in_sizes[0] / 3;
    int nm = in_sizes[1] / 3;
    int nmax = nf > nm ? nf : nm;
    int pblk = (nmax + 255) / 256;
    if (pblk > 128) pblk = 128;

    prep_kernel<<<pblk, 256>>>(fx, mv, mat, tr, nf, nm, out, pblk);
    grid_kernel<<<1, 384>>>(pblk, nf, nm);
    count_kernel<<<pblk, 256>>>(nf, nm);
    scanA_kernel<<<16, 256>>>();
    scanB_kernel<<<1, 32>>>();
    scanC_kernel<<<16, 256>>>();
    scatter_kernel<<<pblk, 256>>>(nf, nm);
    query_kernel<<<dim3((nmax + 255) / 256, 2), 256>>>(out, nm, nf);
    tail_kernel<<<148, 256>>>(nm, nf);
    fin_kernel<<<16, 256>>>(out, nm, nf);
}

// round 9
// speedup vs baseline: 19.1967x; 2.4128x over previous
#include <cuda_runtime.h>
#include <math_constants.h>

// ---------------------------------------------------------------------------
// AffineChamferLoss: exact NN via anisotropic 32^3 CSR grid.
// Query phase is WARP-PER-QUERY (all branches warp-uniform, no stragglers):
//   home cell (lanes stride points) -> 26 neighbors (1 cell/lane, pruned)
//   -> slab r=1 proof -> ring-2 (4 cells/lane, pruned) -> slab r=2 proof
//   -> sample upper bound + z-column sweep (32 columns/lane).
// All bounds exact; boundary cells open-ended outward (clamped outliers).
// ---------------------------------------------------------------------------

#define NMAX   16384
#define G      32
#define CELLS  (G * G * G)     // 32768
#define SEGC   4096
#define INFF   3.0e38f

__device__ float4   g_xbuf[NMAX];         // transformed moving pts (set 1)
__device__ float4   g_ybuf[NMAX];         // fixed pts              (set 0)
__device__ int      g_cellid[2][NMAX];
__device__ unsigned g_cnt[2][CELLS];
__device__ int      g_start[2][CELLS + 16];
__device__ unsigned g_cur[2][CELLS];
__device__ float4   g_sort[2][NMAX];
__device__ float    g_mpart[2][128][6];
__device__ unsigned g_segsum[2][8];
__device__ unsigned g_segoff[2][8];

struct GridI {
    float mnx, mny, mnz;
    float hx, hy, hz;
    float ivx, ivy, ivz;
};
__device__ GridI g_grid[2];

// per-axis distance lower bound from q to cell i (boundary cells open outward)
__device__ __forceinline__ float axdist(float q, float mn, float h, int i) {
    float lo = fmaf((float)i, h, mn);
    float dl = (i > 0)     ? (lo - q)       : -INFF;
    float dr = (i < G - 1) ? (q - (lo + h)) : -INFF;
    return fmaxf(0.0f, fmaxf(dl, dr));
}

// exact min-distance to all cells OUTSIDE the scanned clipped box of radius R
__device__ __forceinline__ float slab_bound(float fr, float h, int c, int R) {
    float b = INFF;
    if (c - R >= 1)     b = fminf(b, h * (fr + (float)R));
    if (c + R <= G - 2) b = fminf(b, h * ((float)(R + 1) - fr));
    return b;
}

__device__ __forceinline__ float warp_min(float v) {
#pragma unroll
    for (int o = 16; o; o >>= 1)
        v = fminf(v, __shfl_xor_sync(0xffffffffu, v, o));
    return v;
}

__device__ __forceinline__ void scan_range(const float4* __restrict__ tb,
                                           int s0, int e0, float4 q,
                                           float& best) {
    for (int p = s0; p < e0; ++p) {
        float4 t = tb[p];
        float ax = t.x - q.x, ay = t.y - q.y, az = t.z - q.z;
        float d2 = fmaf(ax, ax, fmaf(ay, ay, az * az));
        best = fminf(best, d2);
    }
}

// ---- 256-thread block exclusive scan ---------------------------------------
__device__ __forceinline__ unsigned excl_scan_256(unsigned v, unsigned* wsm) {
    int lane = threadIdx.x & 31, wp = threadIdx.x >> 5;
    unsigned inc = v;
#pragma unroll
    for (int o = 1; o < 32; o <<= 1) {
        unsigned n = __shfl_up_sync(0xffffffffu, inc, o);
        if (lane >= o) inc += n;
    }
    if (lane == 31) wsm[wp] = inc;
    __syncthreads();
    if (wp == 0) {
        unsigned ws = (lane < 8) ? wsm[lane] : 0u;
#pragma unroll
        for (int o = 1; o < 8; o <<= 1) {
            unsigned n = __shfl_up_sync(0xffffffffu, ws, o);
            if (lane >= o) ws += n;
        }
        if (lane < 8) wsm[lane] = ws;
    }
    __syncthreads();
    unsigned off = wp ? wsm[wp - 1] : 0u;
    return off + inc - v;
}

// ---------------------------------------------------------------------------
// K1: transform + moment partials + zero counts/out
__global__ void prep_kernel(const float* __restrict__ fx,
                            const float* __restrict__ mv,
                            const float* __restrict__ mat,
                            const float* __restrict__ tr,
                            int nf, int nm, float* out, int nblocks) {
    __shared__ float sm[12];
    int t = threadIdx.x;
    if (t < 12) sm[t] = 0.0f;
    __syncthreads();

    int i = blockIdx.x * 256 + t;

    float mx0 = 0.f, mx1 = 0.f, mx2 = 0.f, mq0 = 0.f, mq1 = 0.f, mq2 = 0.f;
    if (i < nm) {
        float p0 = mv[3*i+0], p1 = mv[3*i+1], p2 = mv[3*i+2];
        float x0 = fmaf(p2, mat[6], fmaf(p1, mat[3], fmaf(p0, mat[0], tr[0])));
        float x1 = fmaf(p2, mat[7], fmaf(p1, mat[4], fmaf(p0, mat[1], tr[1])));
        float x2 = fmaf(p2, mat[8], fmaf(p1, mat[5], fmaf(p0, mat[2], tr[2])));
        g_xbuf[i] = make_float4(x0, x1, x2, 0.0f);
        mx0 = x0; mx1 = x1; mx2 = x2;
        mq0 = x0 * x0; mq1 = x1 * x1; mq2 = x2 * x2;
    }
    float fy0 = 0.f, fy1 = 0.f, fy2 = 0.f, fq0 = 0.f, fq1 = 0.f, fq2 = 0.f;
    if (i < nf) {
        float y0 = fx[3*i+0], y1 = fx[3*i+1], y2 = fx[3*i+2];
        g_ybuf[i] = make_float4(y0, y1, y2, 0.0f);
        fy0 = y0; fy1 = y1; fy2 = y2;
        fq0 = y0 * y0; fq1 = y1 * y1; fq2 = y2 * y2;
    }

    float vals[12] = {fy0, fy1, fy2, fq0, fq1, fq2, mx0, mx1, mx2, mq0, mq1, mq2};
#pragma unroll
    for (int a = 0; a < 12; a++) {
        float v = vals[a];
#pragma unroll
        for (int o = 16; o; o >>= 1) v += __shfl_down_sync(0xffffffffu, v, o);
        if ((t & 31) == 0) atomicAdd(&sm[a], v);
    }
    __syncthreads();
    if (t < 12) g_mpart[t / 6][blockIdx.x][t % 6] = sm[t];

    unsigned* cn = &g_cnt[0][0];
    int tid = blockIdx.x * 256 + t;
    int stride = nblocks * 256;
    for (int k = tid; k < 2 * CELLS; k += stride) cn[k] = 0u;
    if (tid == 0) out[0] = 0.0f;
}

// K2: reduce moment partials, build per-axis robust grid geometry
__global__ void grid_kernel(int nblocks, int nf, int nm) {
    __shared__ float bb[12];
    int t = threadIdx.x;
    int slot = t >> 5, lane = t & 31;
    if (slot < 12) {
        int s = slot / 6, k = slot % 6;
        float v = 0.0f;
        for (int j = lane; j < nblocks; j += 32) v += g_mpart[s][j][k];
#pragma unroll
        for (int o = 16; o; o >>= 1) v += __shfl_down_sync(0xffffffffu, v, o);
        if (lane == 0) bb[slot] = v;
    }
    __syncthreads();
    if (t < 2) {
        int s = t;
        float n = (float)(s ? nm : nf);
        float inv = 1.0f / n;
        float mean[3], sig[3];
#pragma unroll
        for (int a = 0; a < 3; a++) {
            mean[a] = bb[s*6+a] * inv;
            float var = bb[s*6+3+a] * inv - mean[a] * mean[a];
            sig[a] = sqrtf(fmaxf(var, 1e-8f));
        }
        GridI gi;
        gi.mnx = mean[0] - 3.0f * sig[0];
        gi.mny = mean[1] - 3.0f * sig[1];
        gi.mnz = mean[2] - 3.0f * sig[2];
        gi.hx = 6.0f * sig[0] / (float)G;
        gi.hy = 6.0f * sig[1] / (float)G;
        gi.hz = 6.0f * sig[2] / (float)G;
        gi.ivx = 1.0f / gi.hx; gi.ivy = 1.0f / gi.hy; gi.ivz = 1.0f / gi.hz;
        g_grid[s] = gi;
    }
}

// K3: cell ids + counts
__global__ void count_kernel(int nf, int nm) {
    int i = blockIdx.x * blockDim.x + threadIdx.x;
    GridI a = g_grid[0], b = g_grid[1];
    if (i < nf) {
        float4 p = g_ybuf[i];
        int ix = min(G - 1, max(0, (int)floorf((p.x - a.mnx) * a.ivx)));
        int iy = min(G - 1, max(0, (int)floorf((p.y - a.mny) * a.ivy)));
        int iz = min(G - 1, max(0, (int)floorf((p.z - a.mnz) * a.ivz)));
        int c = (ix << 10) | (iy << 5) | iz;
        g_cellid[0][i] = c;
        atomicAdd(&g_cnt[0][c], 1u);
    }
    if (i < nm) {
        float4 p = g_xbuf[i];
        int ix = min(G - 1, max(0, (int)floorf((p.x - b.mnx) * b.ivx)));
        int iy = min(G - 1, max(0, (int)floorf((p.y - b.mny) * b.ivy)));
        int iz = min(G - 1, max(0, (int)floorf((p.z - b.mnz) * b.ivz)));
        int c = (ix << 10) | (iy << 5) | iz;
        g_cellid[1][i] = c;
        atomicAdd(&g_cnt[1][c], 1u);
    }
}

// K4: local scan of 4096-cell segments (16 blocks: set = b>>3, seg = b&7)
__global__ void __launch_bounds__(256)
scanA_kernel() {
    __shared__ unsigned wsm[8];
    int s = blockIdx.x >> 3, seg = blockIdx.x & 7;
    int t = threadIdx.x;
    const uint4* c4 = reinterpret_cast<const uint4*>(&g_cnt[s][seg * SEGC]);
    unsigned cnts[16];
#pragma unroll
    for (int j = 0; j < 4; j++) {
        uint4 v = c4[t * 4 + j];
        cnts[j*4+0] = v.x; cnts[j*4+1] = v.y; cnts[j*4+2] = v.z; cnts[j*4+3] = v.w;
    }
    unsigned tot = 0;
#pragma unroll
    for (int j = 0; j < 16; j++) tot += cnts[j];

    unsigned e = excl_scan_256(tot, wsm);

    unsigned run = e;
    int st[16];
#pragma unroll
    for (int j = 0; j < 16; j++) { st[j] = (int)run; run += cnts[j]; }

    int4* st4 = reinterpret_cast<int4*>(&g_start[s][seg * SEGC]);
#pragma unroll
    for (int j = 0; j < 4; j++)
        st4[t * 4 + j] = make_int4(st[j*4+0], st[j*4+1], st[j*4+2], st[j*4+3]);
    if (t == 255) g_segsum[s][seg] = run;
}

// K5: 1-warp scan of segment sums for both sets
__global__ void scanB_kernel() {
    int lane = threadIdx.x;
    for (int s = 0; s < 2; ++s) {
        unsigned v = (lane < 8) ? g_segsum[s][lane] : 0u;
        unsigned inc = v;
#pragma unroll
        for (int o = 1; o < 8; o <<= 1) {
            unsigned n = __shfl_up_sync(0xffffffffu, inc, o);
            if (lane >= o) inc += n;
        }
        if (lane < 8) g_segoff[s][lane] = inc - v;
        if (lane == 7) g_start[s][CELLS] = (int)inc;
    }
}

// K6: apply segment offsets, write cursors
__global__ void __launch_bounds__(256)
scanC_kernel() {
    int s = blockIdx.x >> 3, seg = blockIdx.x & 7;
    int t = threadIdx.x;
    int off = (int)g_segoff[s][seg];
    int4* st4 = reinterpret_cast<int4*>(&g_start[s][seg * SEGC]);
    int4* cu4 = reinterpret_cast<int4*>(&g_cur[s][seg * SEGC]);
#pragma unroll
    for (int j = 0; j < 4; j++) {
        int4 v = st4[t * 4 + j];
        v.x += off; v.y += off; v.z += off; v.w += off;
        st4[t * 4 + j] = v;
        cu4[t * 4 + j] = v;
    }
}

// K7: scatter into CSR order
__global__ void scatter_kernel(int nf, int nm) {
    int i = blockIdx.x * blockDim.x + threadIdx.x;
    if (i < nf) {
        int c = g_cellid[0][i];
        unsigned p = atomicAdd(&g_cur[0][c], 1u);
        g_sort[0][p] = g_ybuf[i];
    }
    if (i < nm) {
        int c = g_cellid[1][i];
        unsigned p = atomicAdd(&g_cur[1][c], 1u);
        g_sort[1][p] = g_xbuf[i];
    }
}

// K8: WARP-PER-QUERY exact NN + mean reduction
__global__ void __launch_bounds__(256)
query_kernel(float* out, int nm, int nf) {
    const int dir = blockIdx.y;                 // 0: mov->fixed, 1: fixed->mov
    const int nq = dir ? nf : nm;
    const int nt = dir ? nm : nf;               // target count
    const float4* __restrict__ qb = g_sort[1 - dir];   // sorted queries
    const float4* __restrict__ tb = g_sort[dir];
    const int*    __restrict__ cs = &g_start[dir][0];
    GridI gi = g_grid[dir];

    int wid = threadIdx.x >> 5, lane = threadIdx.x & 31;
    int qi = blockIdx.x * 8 + wid;

    float res = 0.0f;
    if (qi < nq) {
        float4 q = qb[qi];
        float rx = (q.x - gi.mnx) * gi.ivx;
        float ry = (q.y - gi.mny) * gi.ivy;
        float rz = (q.z - gi.mnz) * gi.ivz;
        int cx = min(G - 1, max(0, (int)floorf(rx)));
        int cy = min(G - 1, max(0, (int)floorf(ry)));
        int cz = min(G - 1, max(0, (int)floorf(rz)));
        float fxr = rx - (float)cx;
        float fyr = ry - (float)cy;
        float fzr = rz - (float)cz;

        // ---- stage 1: home cell, lanes stride points ----
        int home = (cx << 10) | (cy << 5) | cz;
        float lb = INFF;
        {
            int s0 = cs[home], e0 = cs[home + 1];
            for (int p = s0 + lane; p < e0; p += 32) {
                float4 t = tb[p];
                float ax = t.x - q.x, ay = t.y - q.y, az = t.z - q.z;
                lb = fminf(lb, fmaf(ax, ax, fmaf(ay, ay, az * az)));
            }
        }
        float best = warp_min(lb);

        // ---- stage 2: 26 neighbors, one cell per lane, pruned vs best ----
        lb = best;
        if (lane < 26) {
            int l = lane + (lane >= 13);        // skip center (index 13)
            int a = l / 9 - 1, b = (l / 3) % 3 - 1, c = l % 3 - 1;
            int ix = cx + a, iy = cy + b, iz = cz + c;
            if ((unsigned)ix < G && (unsigned)iy < G && (unsigned)iz < G) {
                float ddx = axdist(q.x, gi.mnx, gi.hx, ix);
                float ddy = axdist(q.y, gi.mny, gi.hy, iy);
                float ddz = axdist(q.z, gi.mnz, gi.hz, iz);
                float bnd = fmaf(ddx, ddx, fmaf(ddy, ddy, ddz * ddz));
                if (bnd < lb) {
                    int cell = (ix << 10) | (iy << 5) | iz;
                    scan_range(tb, cs[cell], cs[cell + 1], q, lb);
                }
            }
        }
        best = warp_min(lb);

        float b1 = fminf(fminf(slab_bound(fxr, gi.hx, cx, 1),
                               slab_bound(fyr, gi.hy, cy, 1)),
                         slab_bound(fzr, gi.hz, cz, 1));
        if (b1 * b1 < best) {
            // ---- stage 3: ring-2 shell, 4 cells per lane ----
            lb = best;
            for (int k = lane; k < 125; k += 32) {
                int a = k / 25 - 2, b = (k / 5) % 5 - 2, c = k % 5 - 2;
                if (max(max(abs(a), abs(b)), abs(c)) != 2) continue;
                int ix = cx + a, iy = cy + b, iz = cz + c;
                if ((unsigned)ix >= G || (unsigned)iy >= G || (unsigned)iz >= G)
                    continue;
                float ddx = axdist(q.x, gi.mnx, gi.hx, ix);
                float ddy = axdist(q.y, gi.mny, gi.hy, iy);
                float ddz = axdist(q.z, gi.mnz, gi.hz, iz);
                float bnd = fmaf(ddx, ddx, fmaf(ddy, ddy, ddz * ddz));
                if (bnd < lb) {
                    int cell = (ix << 10) | (iy << 5) | iz;
                    scan_range(tb, cs[cell], cs[cell + 1], q, lb);
                }
            }
            best = warp_min(lb);

            float b2 = fminf(fminf(slab_bound(fxr, gi.hx, cx, 2),
                                   slab_bound(fyr, gi.hy, cy, 2)),
                             slab_bound(fzr, gi.hz, cz, 2));
            if (b2 * b2 < best) {
                // ---- stage 4: sample upper bound + z-column sweep ----
                lb = best;
                int p = lane * (nt >> 5);
                if (p < nt) {
                    float4 t = tb[p];
                    float ax = t.x - q.x, ay = t.y - q.y, az = t.z - q.z;
                    lb = fminf(lb, fmaf(ax, ax, fmaf(ay, ay, az * az)));
                }
                lb = warp_min(lb);

                float uz = rz;                  // z in cell coords
                for (int col = lane; col < G * G; col += 32) {
                    int ix = col >> 5, iy = col & 31;
                    float ddx = axdist(q.x, gi.mnx, gi.hx, ix);
                    float ddy = axdist(q.y, gi.mny, gi.hy, iy);
                    float dxy2 = fmaf(ddx, ddx, ddy * ddy);
                    float rem = lb - dxy2;
                    if (rem <= 0.0f) continue;
                    float sv = sqrtf(rem) * gi.ivz;
                    int zlo = min(G - 1, max(0, (int)floorf(uz - sv)));
                    int zhi = min(G - 1, max(0, (int)floorf(uz + sv)));
                    int base = (ix << 10) | (iy << 5);
                    scan_range(tb, cs[base + zlo], cs[base + zhi + 1], q, lb);
                }
                best = warp_min(lb);
            }
        }
        res = best / (float)nq;
    }

    // block reduce (one value per warp) + atomicAdd
    __shared__ float ws[8];
    if (lane == 0) ws[wid] = res;
    __syncthreads();
    if (wid == 0) {
        float acc = (lane < 8) ? ws[lane] : 0.0f;
#pragma unroll
        for (int o = 4; o; o >>= 1) acc += __shfl_down_sync(0xffffffffu, acc, o);
        if (lane == 0) atomicAdd(out, acc);
    }
}

// ---------------------------------------------------------------------------
extern "C" void kernel_launch(void* const* d_in, const int* in_sizes, int n_in,
                              void* d_out, int out_size) {
    const float* fx  = (const float*)d_in[0];
    const float* mv  = (const float*)d_in[1];
    const float* mat = (const float*)d_in[2];
    const float* tr  = (const float*)d_in[3];
    float* out = (float*)d_out;

    int nf = in_sizes[0] / 3;
    int nm = in_sizes[1] / 3;
    int nmax = nf > nm ? nf : nm;
    int pblk = (nmax + 255) / 256;
    if (pblk > 128) pblk = 128;

    prep_kernel<<<pblk, 256>>>(fx, mv, mat, tr, nf, nm, out, pblk);
    grid_kernel<<<1, 384>>>(pblk, nf, nm);
    count_kernel<<<pblk, 256>>>(nf, nm);
    scanA_kernel<<<16, 256>>>();
    scanB_kernel<<<1, 32>>>();
    scanC_kernel<<<16, 256>>>();
    scatter_kernel<<<pblk, 256>>>(nf, nm);
    query_kernel<<<dim3((nmax + 7) / 8, 2), 256>>>(out, nm, nf);
}